// round 15
// baseline (speedup 1.0000x reference)
#include <cuda_runtime.h>
#include <cuda_fp16.h>
#include <cstdint>

#define NN 100000
#define EE 600000
#define FF 512
#define HH 256
#define HG 128   // H2

typedef __half fp16;
typedef __half2 fp162;

// ---------------- scratch (static __device__ — no allocations) ----------------
__device__ fp16 g_XW1[(size_t)NN * HH];
__device__ fp16 g_XW2[(size_t)NN * HH];   // GEMM2 out; later branch-B MEAN
__device__ fp16 g_X0 [(size_t)NN * HH];   // r2, then += r1
__device__ fp16 g_G1 [(size_t)NN * HH];
__device__ fp16 g_MEAN[(size_t)NN * HH];  // branch-A MEAN
__device__ float g_dis1[NN], g_dis2[NN], g_inv1[NN], g_inv2[NN];
__device__ int   g_deg1[NN], g_deg2[NN];
__device__ int   g_rp1[NN + 1], g_rp2[NN + 1];
__device__ int   g_cur1[NN + 1], g_cur2[NN + 1];
__device__ int   g_col1[EE], g_col2[EE];
__device__ float g_part[1600];

// pre-transposed fp16 weights, layout WT[n*K + k]
#define OWG1 0
#define OWG2 131072
#define OWL1 262144
#define OWR1 294912
#define OWL2 327680
#define OWR2 360448
#define OWM1 393216
__device__ fp16 g_wt[409600];

// ---------------- weight transpose ----------------
__global__ void k_wt(const float* __restrict__ W, fp16* __restrict__ th, int K, int M) {
    int i = blockIdx.x * blockDim.x + threadIdx.x;
    if (i < K * M) {
        int k = i / M, n = i % M;
        th[(size_t)n * K + k] = __float2half(W[i]);
    }
}

// ---------------- MMA GEMM common ----------------
#define LDSB 80          // bytes per smem row (32 fp16 = 64B + 16B pad)
#define STG_T 10240      // 128 rows * 80B
#define OFF_A  0
#define OFF_B  30720     // after 3 A stages
#define SMEM_MMA 61440   // 3 * (A + B)
// fused kernel extras
#define P_STRIDE 272     // bank-conflict-free P-tile row stride
#define PH2B 61440       // phase-2 B region (4 chunks * 10240)
#define SMEM_FUSE 102400

__device__ __forceinline__ void cpa16(uint32_t dst, const void* src) {
    asm volatile("cp.async.ca.shared.global [%0], [%1], 16;"
                 :: "r"(dst), "l"(src));
}

__device__ __forceinline__ void mma_fp16(float* c, const uint32_t* a, const uint32_t* b) {
    asm volatile(
        "mma.sync.aligned.m16n8k16.row.col.f32.f16.f16.f32 "
        "{%0,%1,%2,%3}, {%4,%5,%6,%7}, {%8,%9}, {%0,%1,%2,%3};"
        : "+f"(c[0]), "+f"(c[1]), "+f"(c[2]), "+f"(c[3])
        : "r"(a[0]), "r"(a[1]), "r"(a[2]), "r"(a[3]), "r"(b[0]), "r"(b[1]));
}

__device__ __forceinline__ uint32_t pkh(float a, float b) {
    fp162 h = __float22half2_rn(make_float2(a, b));
    return *(uint32_t*)&h;
}

// ---------------- plain GEMM (GCN layer; A32 = fp32 A converted in-kernel) --------
template<bool A32>
__global__ void __launch_bounds__(256, 2)
k_mma(const void* __restrict__ A1v, const fp16* __restrict__ W1, int K1,
      fp16* __restrict__ C, int M)
{
    extern __shared__ __align__(16) char smem[];
    const uint32_t sb = (uint32_t)__cvta_generic_to_shared(smem);
    const int tid = threadIdx.x;
    const int wid = tid >> 5, lane = tid & 31;
    const int warp_m = wid & 1, warp_n = wid >> 1;
    const int rowBase = blockIdx.y * 128;
    const int colBase = blockIdx.x * 128;

    const int total = K1 >> 5;

    float acc[4][4][4];
#pragma unroll
    for (int i = 0; i < 4; i++)
#pragma unroll
        for (int j = 0; j < 4; j++)
#pragma unroll
            for (int q = 0; q < 4; q++) acc[i][j][q] = 0.0f;

    uint32_t aregs[8];

    auto issue = [&](int it, int stage) {
        int k0 = it << 5;
        if (!A32) {
            const fp16* A = (const fp16*)A1v;
#pragma unroll
            for (int i = 0; i < 2; i++) {
                int idx = tid + i * 256;
                int r = idx >> 2, part = idx & 3;
                int gr = rowBase + r;
                uint32_t d = sb + OFF_A + stage * STG_T + r * LDSB + part * 16;
                if (gr < NN) cpa16(d, A + (size_t)gr * K1 + k0 + part * 8);
                else asm volatile("st.shared.v4.b32 [%0], {%1,%1,%1,%1};" :: "r"(d), "r"(0));
            }
        }
#pragma unroll
        for (int i = 0; i < 2; i++) {
            int idx = tid + i * 256;
            int n = idx >> 2, part = idx & 3;
            int gn = colBase + n;
            uint32_t d = sb + OFF_B + stage * STG_T + n * LDSB + part * 16;
            cpa16(d, W1 + (size_t)gn * K1 + k0 + part * 8);
        }
        asm volatile("cp.async.commit_group;");
    };

    auto loadAreg = [&](int it) {
        if (A32) {
            const float* Af = (const float*)A1v;
            int k0 = it << 5;
            int gr = rowBase + (tid >> 1);
            const float* p = Af + (size_t)gr * K1 + k0 + (tid & 1) * 16;
#pragma unroll
            for (int j = 0; j < 4; j++) {
                float4 v = (gr < NN) ? *(const float4*)(p + 4 * j)
                                     : make_float4(0.f, 0.f, 0.f, 0.f);
                aregs[2 * j] = pkh(v.x, v.y);
                aregs[2 * j + 1] = pkh(v.z, v.w);
            }
        }
    };

    auto storeAreg = [&](int stage) {
        if (A32) {
            uint32_t d = sb + OFF_A + stage * STG_T + (tid >> 1) * LDSB + (tid & 1) * 32;
            asm volatile("st.shared.v4.b32 [%0], {%1,%2,%3,%4};"
                         :: "r"(d), "r"(aregs[0]), "r"(aregs[1]),
                            "r"(aregs[2]), "r"(aregs[3]));
            asm volatile("st.shared.v4.b32 [%0], {%1,%2,%3,%4};"
                         :: "r"(d + 16), "r"(aregs[4]), "r"(aregs[5]),
                            "r"(aregs[6]), "r"(aregs[7]));
        }
    };

    auto compute = [&](int stage) {
#pragma unroll
        for (int ks = 0; ks < 2; ks++) {
            const int kk = ks * 16;
            uint32_t af[4][4];
#pragma unroll
            for (int mi = 0; mi < 4; mi++) {
                int row = warp_m * 64 + mi * 16 + (lane & 15);
                int kc = kk + ((lane >> 4) << 3);
                uint32_t ad = sb + OFF_A + stage * STG_T + row * LDSB + kc * 2;
                asm volatile("ldmatrix.sync.aligned.m8n8.x4.shared.b16 "
                             "{%0,%1,%2,%3}, [%4];"
                             : "=r"(af[mi][0]), "=r"(af[mi][1]),
                               "=r"(af[mi][2]), "=r"(af[mi][3]) : "r"(ad));
            }
            uint32_t bh[4][2];
#pragma unroll
            for (int pair = 0; pair < 2; pair++) {
                int rn = warp_n * 32 + pair * 16 + ((lane >> 4) << 3) + (lane & 7);
                int kc = kk + ((lane >> 3) & 1) * 8;
                uint32_t off = sb + OFF_B + stage * STG_T + rn * LDSB + kc * 2;
                asm volatile("ldmatrix.sync.aligned.m8n8.x4.shared.b16 "
                             "{%0,%1,%2,%3}, [%4];"
                             : "=r"(bh[2 * pair][0]), "=r"(bh[2 * pair][1]),
                               "=r"(bh[2 * pair + 1][0]), "=r"(bh[2 * pair + 1][1])
                             : "r"(off));
            }
#pragma unroll
            for (int mi = 0; mi < 4; mi++)
#pragma unroll
                for (int ni = 0; ni < 4; ni++)
                    mma_fp16(acc[mi][ni], af[mi], bh[ni]);
        }
    };

    issue(0, 0);
    loadAreg(0);
    storeAreg(0);
    if (total > 1) { issue(1, 1); loadAreg(1); storeAreg(1); }

    for (int it = 0; it < total; ++it) {
        const int stage = it % 3;
        if (it + 1 < total) asm volatile("cp.async.wait_group 1;");
        else               asm volatile("cp.async.wait_group 0;");
        __syncthreads();
        if (it + 2 < total) {
            issue(it + 2, (it + 2) % 3);
            loadAreg(it + 2);
            storeAreg((it + 2) % 3);
        }
        compute(stage);
    }

    const int g = lane >> 2, tg = lane & 3;
#pragma unroll
    for (int mi = 0; mi < 4; mi++) {
#pragma unroll
        for (int ni = 0; ni < 4; ni++) {
            int col = colBase + warp_n * 32 + ni * 8 + tg * 2;
            int row = rowBase + warp_m * 64 + mi * 16 + g;
            if (row < NN) {
                fp162 h = __float22half2_rn(make_float2(acc[mi][ni][0], acc[mi][ni][1]));
                *(fp162*)(C + (size_t)row * M + col) = h;
            }
            if (row + 8 < NN) {
                fp162 h = __float22half2_rn(make_float2(acc[mi][ni][2], acc[mi][ni][3]));
                *(fp162*)(C + (size_t)(row + 8) * M + col) = h;
            }
        }
    }
}

// ---------------- fused SAGE-GEMM + MLP-GEMM + LayerNorm-dot ----------------
// Phase 1: P = relu(MEAN@Wl + feat@Wr + bl)  [128 rows x 128 cols, CTA-local]
// Phase 2: T = P@Wm1 + bm1; LayerNorm(T)*lnw+lnb dot wm2 -> g_part[poff+blk]
__global__ void __launch_bounds__(256, 2)
k_fuse(const fp16* __restrict__ A1p, const fp16* __restrict__ W1,
       const fp16* __restrict__ A2p, const fp16* __restrict__ W2,
       const float* __restrict__ bl, const fp16* __restrict__ Wm,
       const float* __restrict__ bm1,
       const float* __restrict__ lnw, const float* __restrict__ lnb,
       const float* __restrict__ wm2, const float* __restrict__ bm2, int poff)
{
    extern __shared__ __align__(16) char smem[];
    const uint32_t sb = (uint32_t)__cvta_generic_to_shared(smem);
    const int tid = threadIdx.x;
    const int wid = tid >> 5, lane = tid & 31;
    const int warp_m = wid & 1, warp_n = wid >> 1;
    const int rowBase = blockIdx.y * 128;

    const int n1 = HH >> 5;          // 8
    const int total = 2 * n1;        // 16

    float acc[4][4][4];
#pragma unroll
    for (int i = 0; i < 4; i++)
#pragma unroll
        for (int j = 0; j < 4; j++)
#pragma unroll
            for (int q = 0; q < 4; q++) acc[i][j][q] = 0.0f;

    auto issue = [&](int it, int stage) {
        const fp16* A = (it < n1) ? A1p : A2p;
        const fp16* W = (it < n1) ? W1 : W2;
        int k0 = ((it < n1) ? it : it - n1) << 5;
#pragma unroll
        for (int i = 0; i < 2; i++) {
            int idx = tid + i * 256;
            int r = idx >> 2, part = idx & 3;
            int gr = rowBase + r;
            uint32_t d = sb + OFF_A + stage * STG_T + r * LDSB + part * 16;
            if (gr < NN) cpa16(d, A + (size_t)gr * HH + k0 + part * 8);
            else asm volatile("st.shared.v4.b32 [%0], {%1,%1,%1,%1};" :: "r"(d), "r"(0));
        }
#pragma unroll
        for (int i = 0; i < 2; i++) {
            int idx = tid + i * 256;
            int n = idx >> 2, part = idx & 3;
            uint32_t d = sb + OFF_B + stage * STG_T + n * LDSB + part * 16;
            cpa16(d, W + (size_t)n * HH + k0 + part * 8);
        }
        asm volatile("cp.async.commit_group;");
    };

    auto compute = [&](uint32_t abase, int astride, int koff, uint32_t bbase) {
#pragma unroll
        for (int ks = 0; ks < 2; ks++) {
            const int kk = ks * 16;
            uint32_t af[4][4];
#pragma unroll
            for (int mi = 0; mi < 4; mi++) {
                int row = warp_m * 64 + mi * 16 + (lane & 15);
                int kc = koff + kk + ((lane >> 4) << 3);
                uint32_t ad = abase + row * astride + kc * 2;
                asm volatile("ldmatrix.sync.aligned.m8n8.x4.shared.b16 "
                             "{%0,%1,%2,%3}, [%4];"
                             : "=r"(af[mi][0]), "=r"(af[mi][1]),
                               "=r"(af[mi][2]), "=r"(af[mi][3]) : "r"(ad));
            }
            uint32_t bh[4][2];
#pragma unroll
            for (int pair = 0; pair < 2; pair++) {
                int rn = warp_n * 32 + pair * 16 + ((lane >> 4) << 3) + (lane & 7);
                int kc = kk + ((lane >> 3) & 1) * 8;
                uint32_t off = bbase + rn * LDSB + kc * 2;
                asm volatile("ldmatrix.sync.aligned.m8n8.x4.shared.b16 "
                             "{%0,%1,%2,%3}, [%4];"
                             : "=r"(bh[2 * pair][0]), "=r"(bh[2 * pair][1]),
                               "=r"(bh[2 * pair + 1][0]), "=r"(bh[2 * pair + 1][1])
                             : "r"(off));
            }
#pragma unroll
            for (int mi = 0; mi < 4; mi++)
#pragma unroll
                for (int ni = 0; ni < 4; ni++)
                    mma_fp16(acc[mi][ni], af[mi], bh[ni]);
        }
    };

    // preload all 4 Wm1 k-chunks into PH2B (joins stage-0 cp.async group)
#pragma unroll
    for (int c = 0; c < 4; c++) {
#pragma unroll
        for (int i = 0; i < 2; i++) {
            int idx = tid + i * 256;
            int n = idx >> 2, part = idx & 3;
            uint32_t d = sb + PH2B + c * STG_T + n * LDSB + part * 16;
            cpa16(d, Wm + (size_t)n * HG + c * 32 + part * 8);
        }
    }
    issue(0, 0);
    issue(1, 1);

    // ---- phase 1 mainloop (16 iters) ----
    for (int it = 0; it < total; ++it) {
        const int stage = it % 3;
        if (it + 1 < total) asm volatile("cp.async.wait_group 1;");
        else               asm volatile("cp.async.wait_group 0;");
        __syncthreads();
        if (it + 2 < total) issue(it + 2, (it + 2) % 3);
        compute(sb + OFF_A + stage * STG_T, LDSB, 0, sb + OFF_B + stage * STG_T);
    }

    const int g = lane >> 2, tg = lane & 3;

    // ---- store P = relu(acc + bl) to smem (stride 272, conflict-free) ----
    __syncthreads();
    {
#pragma unroll
        for (int ni = 0; ni < 4; ni++) {
            int col = warp_n * 32 + ni * 8 + tg * 2;
            float b0 = bl[col], b1 = bl[col + 1];
#pragma unroll
            for (int mi = 0; mi < 4; mi++) {
                int row = warp_m * 64 + mi * 16 + g;
                uint32_t d = sb + row * P_STRIDE + col * 2;
                uint32_t v0 = pkh(fmaxf(acc[mi][ni][0] + b0, 0.f),
                                  fmaxf(acc[mi][ni][1] + b1, 0.f));
                uint32_t v1 = pkh(fmaxf(acc[mi][ni][2] + b0, 0.f),
                                  fmaxf(acc[mi][ni][3] + b1, 0.f));
                asm volatile("st.shared.b32 [%0], %1;" :: "r"(d), "r"(v0));
                asm volatile("st.shared.b32 [%0], %1;" :: "r"(d + 8 * P_STRIDE), "r"(v1));
            }
        }
    }
    __syncthreads();

    // ---- phase 2: T = P @ Wm1 ----
#pragma unroll
    for (int i = 0; i < 4; i++)
#pragma unroll
        for (int j = 0; j < 4; j++)
#pragma unroll
            for (int q = 0; q < 4; q++) acc[i][j][q] = 0.0f;
    for (int c = 0; c < 4; c++)
        compute(sb, P_STRIDE, c * 32, sb + PH2B + c * STG_T);

    // ---- LayerNorm + dot(wm2) epilogue ----
    __syncthreads();
    float* sred = (float*)smem;             // [128][8]
    float* sdot = (float*)(smem + 4096);    // [128][4]
    float* sblk = (float*)(smem + 6144);    // [4]

    float b0[4], b1[4], w0[4], w1[4], l0[4], l1[4], m0[4], m1[4];
#pragma unroll
    for (int ni = 0; ni < 4; ni++) {
        int c = warp_n * 32 + ni * 8 + tg * 2;
        b0[ni] = bm1[c];  b1[ni] = bm1[c + 1];
        w0[ni] = lnw[c];  w1[ni] = lnw[c + 1];
        l0[ni] = lnb[c];  l1[ni] = lnb[c + 1];
        m0[ni] = wm2[c];  m1[ni] = wm2[c + 1];
    }

#pragma unroll
    for (int mi = 0; mi < 4; mi++) {
#pragma unroll
        for (int half = 0; half < 2; half++) {
            float ps = 0.f, pq = 0.f;
#pragma unroll
            for (int ni = 0; ni < 4; ni++) {
                float v = acc[mi][ni][half * 2] + b0[ni];
                float u = acc[mi][ni][half * 2 + 1] + b1[ni];
                ps += v + u;
                pq += v * v + u * u;
            }
            ps += __shfl_xor_sync(0xffffffffu, ps, 1);
            ps += __shfl_xor_sync(0xffffffffu, ps, 2);
            pq += __shfl_xor_sync(0xffffffffu, pq, 1);
            pq += __shfl_xor_sync(0xffffffffu, pq, 2);
            int r = warp_m * 64 + mi * 16 + g + half * 8;
            if (tg == 0) {
                sred[r * 8 + warp_n * 2] = ps;
                sred[r * 8 + warp_n * 2 + 1] = pq;
            }
        }
    }
    __syncthreads();

#pragma unroll
    for (int mi = 0; mi < 4; mi++) {
#pragma unroll
        for (int half = 0; half < 2; half++) {
            int r = warp_m * 64 + mi * 16 + g + half * 8;
            float sum = sred[r * 8 + 0] + sred[r * 8 + 2] + sred[r * 8 + 4] + sred[r * 8 + 6];
            float sq  = sred[r * 8 + 1] + sred[r * 8 + 3] + sred[r * 8 + 5] + sred[r * 8 + 7];
            float mu = sum * (1.0f / 128.0f);
            float var = sq * (1.0f / 128.0f) - mu * mu;
            float rs = rsqrtf(var + 1e-5f);
            float p = 0.f;
#pragma unroll
            for (int ni = 0; ni < 4; ni++) {
                float v = acc[mi][ni][half * 2] + b0[ni];
                float u = acc[mi][ni][half * 2 + 1] + b1[ni];
                p += ((v - mu) * rs * w0[ni] + l0[ni]) * m0[ni]
                   + ((u - mu) * rs * w1[ni] + l1[ni]) * m1[ni];
            }
            p += __shfl_xor_sync(0xffffffffu, p, 1);
            p += __shfl_xor_sync(0xffffffffu, p, 2);
            if (tg == 0) sdot[r * 4 + warp_n] = p;
        }
    }
    __syncthreads();

    if (tid < 128) {
        int r = tid;
        int grow = rowBase + r;
        float y = 0.f;
        if (grow < NN)
            y = sdot[r * 4] + sdot[r * 4 + 1] + sdot[r * 4 + 2] + sdot[r * 4 + 3] + bm2[0];
#pragma unroll
        for (int o = 16; o; o >>= 1) y += __shfl_xor_sync(0xffffffffu, y, o);
        if ((tid & 31) == 0) sblk[tid >> 5] = y;
    }
    __syncthreads();
    if (tid == 0)
        g_part[poff + blockIdx.y] = sblk[0] + sblk[1] + sblk[2] + sblk[3];
}

// ---------------- small utility kernels ----------------
__global__ void k_zero_int(int* p, int n) {
    int i = blockIdx.x * blockDim.x + threadIdx.x;
    if (i < n) p[i] = 0;
}

__global__ void k_copy_int(int* dst, const int* src, int n) {
    int i = blockIdx.x * blockDim.x + threadIdx.x;
    if (i < n) dst[i] = src[i];
}

__global__ void k_deg(const int* __restrict__ dst, int* __restrict__ deg) {
    int e = blockIdx.x * blockDim.x + threadIdx.x;
    if (e < EE) atomicAdd(&deg[dst[e]], 1);
}

__global__ void k_scan(const int* __restrict__ deg, int* __restrict__ rp, int n) {
    __shared__ int s[1024];
    int t = threadIdx.x;
    int chunk = (n + 1023) >> 10;
    int b = t * chunk;
    int e = b + chunk; if (e > n) e = n;
    int local = 0;
    for (int i = b; i < e && i < n; i++) local += deg[i];
    s[t] = local;
    __syncthreads();
    for (int off = 1; off < 1024; off <<= 1) {
        int v = (t >= off) ? s[t - off] : 0;
        __syncthreads();
        s[t] += v;
        __syncthreads();
    }
    int run = (t == 0) ? 0 : s[t - 1];
    for (int i = b; i < e && i < n; i++) { rp[i] = run; run += deg[i]; }
    if (t == 1023) rp[n] = s[1023];
}

__global__ void k_disinv(const int* __restrict__ deg, float* __restrict__ dis,
                         float* __restrict__ inv) {
    int i = blockIdx.x * blockDim.x + threadIdx.x;
    if (i < NN) {
        float d = (float)deg[i];
        dis[i] = rsqrtf(d + 1.0f);
        inv[i] = 1.0f / fmaxf(d, 1.0f);
    }
}

__global__ void k_place(const int* __restrict__ src, const int* __restrict__ dst,
                        int* __restrict__ cur, int* __restrict__ col) {
    int e = blockIdx.x * blockDim.x + threadIdx.x;
    if (e < EE) {
        int d = dst[e];
        int p = atomicAdd(&cur[d], 1);
        col[p] = src[e];
    }
}

// ---------------- helpers for fp16 gather ----------------
__device__ __forceinline__ void unp8(uint4 v, float* f) {
    float2 a = __half22float2(*(fp162*)&v.x);
    float2 b = __half22float2(*(fp162*)&v.y);
    float2 c = __half22float2(*(fp162*)&v.z);
    float2 d = __half22float2(*(fp162*)&v.w);
    f[0] = a.x; f[1] = a.y; f[2] = b.x; f[3] = b.y;
    f[4] = c.x; f[5] = c.y; f[6] = d.x; f[7] = d.y;
}

__device__ __forceinline__ uint4 pk8(const float* f) {
    fp162 a = __float22half2_rn(make_float2(f[0], f[1]));
    fp162 b = __float22half2_rn(make_float2(f[2], f[3]));
    fp162 c = __float22half2_rn(make_float2(f[4], f[5]));
    fp162 d = __float22half2_rn(make_float2(f[6], f[7]));
    return make_uint4(*(uint32_t*)&a, *(uint32_t*)&b, *(uint32_t*)&c, *(uint32_t*)&d);
}

// ---------------- GCN aggregation (warp per node) ----------------
// mode 0 (graph2, FIRST): X0 = relu(v); G1 = relu(v)+v
// mode 1 (graph1, SECOND): X0 += relu(v)
__global__ void k_gcn(const fp16* __restrict__ xw, const int* __restrict__ rp,
                      const int* __restrict__ col, const float* __restrict__ dis,
                      const float* __restrict__ bias, int mode) {
    int node = blockIdx.x * 8 + (threadIdx.x >> 5);
    int lane = threadIdx.x & 31;
    if (node >= NN) return;

    const uint4* xw4 = (const uint4*)xw;
    float acc[8] = {0, 0, 0, 0, 0, 0, 0, 0};
    int e0 = rp[node], e1 = rp[node + 1];
    for (int e = e0; e < e1; e++) {
        int s = col[e];
        float ds = dis[s];
        float f[8];
        unp8(xw4[(size_t)s * 32 + lane], f);
#pragma unroll
        for (int u = 0; u < 8; u++) acc[u] += f[u] * ds;
    }
    float di = dis[node];
    float dii = di * di;
    float sf[8];
    unp8(xw4[(size_t)node * 32 + lane], sf);
    const float4* b4 = (const float4*)bias;
    float4 bb0 = b4[2 * lane], bb1 = b4[2 * lane + 1];
    float bb[8] = {bb0.x, bb0.y, bb0.z, bb0.w, bb1.x, bb1.y, bb1.z, bb1.w};

    float v[8], r[8];
#pragma unroll
    for (int u = 0; u < 8; u++) {
        v[u] = acc[u] * di + sf[u] * dii + bb[u];
        r[u] = fmaxf(v[u], 0.f);
    }

    size_t o = (size_t)node * 32 + lane;
    uint4* X04 = (uint4*)g_X0;
    if (mode == 0) {
        X04[o] = pk8(r);
        float gg[8];
#pragma unroll
        for (int u = 0; u < 8; u++) gg[u] = r[u] + v[u];
        ((uint4*)g_G1)[o] = pk8(gg);
    } else {
        float xs[8];
        unp8(X04[o], xs);
#pragma unroll
        for (int u = 0; u < 8; u++) xs[u] += r[u];
        X04[o] = pk8(xs);
    }
}

// ---------------- SAGE mean aggregation (warp per node, fp16) ----------
__global__ void k_sage(const fp16* __restrict__ feat, const int* __restrict__ rp,
                       const int* __restrict__ col, const float* __restrict__ inv,
                       fp16* __restrict__ out) {
    int node = blockIdx.x * 8 + (threadIdx.x >> 5);
    int lane = threadIdx.x & 31;
    if (node >= NN) return;

    const uint4* f4 = (const uint4*)feat;
    float acc[8] = {0, 0, 0, 0, 0, 0, 0, 0};
    int e0 = rp[node], e1 = rp[node + 1];
    for (int e = e0; e < e1; e++) {
        int s = col[e];
        float f[8];
        unp8(f4[(size_t)s * 32 + lane], f);
#pragma unroll
        for (int u = 0; u < 8; u++) acc[u] += f[u];
    }
    float ic = inv[node];
#pragma unroll
    for (int u = 0; u < 8; u++) acc[u] *= ic;
    ((uint4*)out)[(size_t)node * 32 + lane] = pk8(acc);
}

// ---------------- final reduction ----------------
__global__ void k_final(float* out) {
    __shared__ float s[1024];
    int t = threadIdx.x;
    float v = 0;
    for (int i = t; i < 1564; i += 1024) v += g_part[i];
    s[t] = v;
    __syncthreads();
    for (int off = 512; off; off >>= 1) {
        if (t < off) s[t] += s[t + off];
        __syncthreads();
    }
    if (t == 0) out[0] = s[0] * (1.0f / (2.0f * (float)NN));
}

// ---------------- host ----------------
static void* symaddr(const void* s) {
    void* p = nullptr;
    cudaGetSymbolAddress(&p, s);
    return p;
}

static cudaStream_t mkstream() {
    cudaStream_t s;
    cudaStreamCreateWithFlags(&s, cudaStreamNonBlocking);
    return s;
}
static cudaEvent_t mkevent() {
    cudaEvent_t e;
    cudaEventCreateWithFlags(&e, cudaEventDisableTiming);
    return e;
}

extern "C" void kernel_launch(void* const* d_in, const int* in_sizes, int n_in,
                              void* d_out, int out_size) {
    static cudaStream_t s1 = mkstream();
    static cudaStream_t s2 = mkstream();
    static cudaEvent_t eF  = mkevent();
    static cudaEvent_t eW2 = mkevent();   // GEMM2 done
    static cudaEvent_t e2  = mkevent();   // CSR + weights done
    static cudaEvent_t eR2 = mkevent();   // gcn_b done (X0=r2, G1 ready)
    static cudaEvent_t eB  = mkevent();   // branch B done

    const float* x   = (const float*)d_in[0];
    const float* x1  = (const float*)d_in[1];
    const int*   ei  = (const int*)d_in[2];
    const int*   ei1 = (const int*)d_in[3];
    const float* Wg1 = (const float*)d_in[4];
    const float* bg1 = (const float*)d_in[5];
    const float* Wg2 = (const float*)d_in[6];
    const float* bg2 = (const float*)d_in[7];
    const float* Wl1 = (const float*)d_in[8];
    const float* bl1 = (const float*)d_in[9];
    const float* Wr1 = (const float*)d_in[10];
    const float* Wl2 = (const float*)d_in[11];
    const float* bl2 = (const float*)d_in[12];
    const float* Wr2 = (const float*)d_in[13];
    const float* Wm1 = (const float*)d_in[14];
    const float* bm1 = (const float*)d_in[15];
    const float* lnw = (const float*)d_in[16];
    const float* lnb = (const float*)d_in[17];
    const float* Wm2 = (const float*)d_in[18];
    const float* bm2 = (const float*)d_in[19];

    const int* src1 = ei;
    const int* dst1 = ei + EE;
    const int* src2 = ei1;
    const int* dst2 = ei1 + EE;

    fp16* XW1  = (fp16*)symaddr(g_XW1);
    fp16* XW2  = (fp16*)symaddr(g_XW2);
    fp16* X0   = (fp16*)symaddr(g_X0);
    fp16* G1   = (fp16*)symaddr(g_G1);
    fp16* MEAN = (fp16*)symaddr(g_MEAN);
    float* dis1 = (float*)symaddr(g_dis1);
    float* dis2 = (float*)symaddr(g_dis2);
    float* inv1 = (float*)symaddr(g_inv1);
    float* inv2 = (float*)symaddr(g_inv2);
    int* deg1 = (int*)symaddr(g_deg1);
    int* deg2 = (int*)symaddr(g_deg2);
    int* rp1  = (int*)symaddr(g_rp1);
    int* rp2  = (int*)symaddr(g_rp2);
    int* cur1 = (int*)symaddr(g_cur1);
    int* cur2 = (int*)symaddr(g_cur2);
    int* col1 = (int*)symaddr(g_col1);
    int* col2 = (int*)symaddr(g_col2);
    fp16* wt = (fp16*)symaddr(g_wt);

    fp16* MEANB = XW2;   // XW2 dead after gcn_b

    const int TB = 256;
    const int gN = (NN + TB - 1) / TB;
    const int gE = (EE + TB - 1) / TB;

    cudaFuncSetAttribute(k_mma<true>,  cudaFuncAttributeMaxDynamicSharedMemorySize, SMEM_MMA);
    cudaFuncSetAttribute(k_mma<false>, cudaFuncAttributeMaxDynamicSharedMemorySize, SMEM_MMA);
    cudaFuncSetAttribute(k_fuse, cudaFuncAttributeMaxDynamicSharedMemorySize, SMEM_FUSE);

    const int GY = (NN + 127) / 128;  // 782
    dim3 g256(HH / 128, GY);          // (2, 782)
    dim3 gF(1, GY);                   // fused kernel
    const int gW = NN / 8;

    // ---- fork ----
    cudaEventRecord(eF, 0);
    cudaStreamWaitEvent(s1, eF, 0);
    cudaStreamWaitEvent(s2, eF, 0);

    // ---- s1: graph-2 chain (fully independent branch B) ----
    k_wt<<<(FF * HH + 255) / 256, 256, 0, s1>>>(Wg2, wt + OWG2, FF, HH);
    k_mma<true><<<g256, 256, SMEM_MMA, s1>>>(x1, wt + OWG2, FF, XW2, HH);
    cudaEventRecord(eW2, s1);

    // ---- s2: CSR build + SAGE/MLP weight transposes ----
    k_wt<<<(HH * HG + 255) / 256, 256, 0, s2>>>(Wl1, wt + OWL1, HH, HG);
    k_wt<<<(HH * HG + 255) / 256, 256, 0, s2>>>(Wr1, wt + OWR1, HH, HG);
    k_wt<<<(HH * HG + 255) / 256, 256, 0, s2>>>(Wl2, wt + OWL2, HH, HG);
    k_wt<<<(HH * HG + 255) / 256, 256, 0, s2>>>(Wr2, wt + OWR2, HH, HG);
    k_wt<<<(HG * HG + 255) / 256, 256, 0, s2>>>(Wm1, wt + OWM1, HG, HG);
    k_zero_int<<<gN, TB, 0, s2>>>(deg1, NN);
    k_zero_int<<<gN, TB, 0, s2>>>(deg2, NN);
    k_deg<<<gE, TB, 0, s2>>>(dst1, deg1);
    k_deg<<<gE, TB, 0, s2>>>(dst2, deg2);
    k_scan<<<1, 1024, 0, s2>>>(deg1, rp1, NN);
    k_scan<<<1, 1024, 0, s2>>>(deg2, rp2, NN);
    k_disinv<<<gN, TB, 0, s2>>>(deg1, dis1, inv1);
    k_disinv<<<gN, TB, 0, s2>>>(deg2, dis2, inv2);
    k_copy_int<<<gN, TB, 0, s2>>>(cur1, rp1, NN);
    k_copy_int<<<gN, TB, 0, s2>>>(cur2, rp2, NN);
    k_place<<<gE, TB, 0, s2>>>(src1, dst1, cur1, col1);
    k_place<<<gE, TB, 0, s2>>>(src2, dst2, cur2, col2);
    cudaEventRecord(e2, s2);

    // ---- s1 continues branch B (needs CSR) ----
    cudaStreamWaitEvent(s1, e2, 0);
    k_gcn<<<gW, 256, 0, s1>>>(XW2, rp2, col2, dis2, bg2, 0);   // X0=r2, G1=r2+v2
    cudaEventRecord(eR2, s1);
    k_sage<<<gW, 256, 0, s1>>>(G1, rp2, col2, inv2, MEANB);
    k_fuse<<<gF, 256, SMEM_FUSE, s1>>>(MEANB, wt + OWL2, G1, wt + OWR2, bl2,
                                       wt + OWM1, bm1, lnw, lnb, Wm2, bm2, 782);
    cudaEventRecord(eB, s1);

    // ---- s0: graph-1 GCN GEMM (serialized after GEMM2 to prioritize branch B) ----
    k_wt<<<(FF * HH + 255) / 256, 256, 0, 0>>>(Wg1, wt + OWG1, FF, HH);
    cudaStreamWaitEvent(0, eW2, 0);
    k_mma<true><<<g256, 256, SMEM_MMA, 0>>>(x, wt + OWG1, FF, XW1, HH);

    // ---- s0: branch A ----
    cudaStreamWaitEvent(0, eR2, 0);
    k_gcn<<<gW, 256, 0, 0>>>(XW1, rp1, col1, dis1, bg1, 1);    // X0 += r1
    k_sage<<<gW, 256, 0, 0>>>(X0, rp1, col1, inv1, MEAN);
    k_fuse<<<gF, 256, SMEM_FUSE, 0>>>(MEAN, wt + OWL1, X0, wt + OWR1, bl1,
                                      wt + OWM1, bm1, lnw, lnb, Wm2, bm2, 0);

    // ---- join + final reduction ----
    cudaStreamWaitEvent(0, eB, 0);
    k_final<<<1, 1024, 0, 0>>>((float*)d_out);
}

// round 16
// speedup vs baseline: 1.0451x; 1.0451x over previous
#include <cuda_runtime.h>
#include <cuda_fp16.h>
#include <cstdint>

#define NN 100000
#define EE 600000
#define FF 512
#define HH 256
#define HG 128   // H2

typedef __half fp16;
typedef __half2 fp162;

// ---------------- scratch (static __device__ — no allocations) ----------------
__device__ fp16 g_XW1[(size_t)NN * HH];
__device__ fp16 g_XW2[(size_t)NN * HH];   // GEMM2 out; later branch-B MEAN
__device__ fp16 g_X0 [(size_t)NN * HH];   // r2, then += r1
__device__ fp16 g_G1 [(size_t)NN * HH];
__device__ fp16 g_MEAN[(size_t)NN * HH];  // branch-A MEAN
__device__ fp16 g_A1 [(size_t)NN * HG];   // branch-A A1
__device__ fp16 g_A1B[(size_t)NN * HG];   // branch-B A1
__device__ float g_dis1[NN], g_dis2[NN], g_inv1[NN], g_inv2[NN];
__device__ int   g_deg1[NN], g_deg2[NN];
__device__ int   g_rp1[NN + 1], g_rp2[NN + 1];
__device__ int   g_cur1[NN + 1], g_cur2[NN + 1];
__device__ int   g_col1[EE], g_col2[EE];
__device__ float g_part[1600];

// pre-transposed fp16 weights, layout WT[n*K + k]
#define OWG1 0
#define OWG2 131072
#define OWL1 262144
#define OWR1 294912
#define OWL2 327680
#define OWR2 360448
#define OWM1 393216
__device__ fp16 g_wt[409600];

// ---------------- weight transpose ----------------
__global__ void k_wt(const float* __restrict__ W, fp16* __restrict__ th, int K, int M) {
    int i = blockIdx.x * blockDim.x + threadIdx.x;
    if (i < K * M) {
        int k = i / M, n = i % M;
        th[(size_t)n * K + k] = __float2half(W[i]);
    }
}

// ---------------- MMA GEMM (TB=256, BM=128, BN=128, BK=32, 3-stage) ----------------
#define LDSB 80          // bytes per smem row (32 fp16 = 64B + 16B pad)
#define STG_T 10240      // 128 rows * 80B
#define OFF_A  0
#define OFF_B  30720     // after 3 A stages
#define SMEM_MMA 61440   // 3 * (A + B)

__device__ __forceinline__ void cpa16(uint32_t dst, const void* src) {
    asm volatile("cp.async.cg.shared.global [%0], [%1], 16;"
                 :: "r"(dst), "l"(src));
}

__device__ __forceinline__ void mma_fp16(float* c, const uint32_t* a, const uint32_t* b) {
    asm volatile(
        "mma.sync.aligned.m16n8k16.row.col.f32.f16.f16.f32 "
        "{%0,%1,%2,%3}, {%4,%5,%6,%7}, {%8,%9}, {%0,%1,%2,%3};"
        : "+f"(c[0]), "+f"(c[1]), "+f"(c[2]), "+f"(c[3])
        : "r"(a[0]), "r"(a[1]), "r"(a[2]), "r"(a[3]), "r"(b[0]), "r"(b[1]));
}

__device__ __forceinline__ uint32_t pkh(float a, float b) {
    fp162 h = __float22half2_rn(make_float2(a, b));
    return *(uint32_t*)&h;
}

// A32: A1v is fp32, converted in-kernel (A2 unused). LN: fused LayerNorm+dot epilogue.
template<bool A32, bool LN>
__global__ void __launch_bounds__(256, 2)
k_mma(const void* __restrict__ A1v, const fp16* __restrict__ W1, int K1,
      const fp16* __restrict__ A2p, const fp16* __restrict__ W2, int K2,
      fp16* __restrict__ C, int M,
      const float* __restrict__ bias, int reluflag,
      const float* __restrict__ lnw, const float* __restrict__ lnb,
      const float* __restrict__ wm2, const float* __restrict__ bm2, int poff)
{
    extern __shared__ __align__(16) char smem[];
    const uint32_t sb = (uint32_t)__cvta_generic_to_shared(smem);
    const int tid = threadIdx.x;
    const int wid = tid >> 5, lane = tid & 31;
    const int warp_m = wid & 1, warp_n = wid >> 1;
    const int rowBase = blockIdx.y * 128;
    const int colBase = blockIdx.x * 128;

    const int n1 = K1 >> 5;
    const int n2 = A2p ? (K2 >> 5) : 0;
    const int total = n1 + n2;

    float acc[4][4][4];
#pragma unroll
    for (int i = 0; i < 4; i++)
#pragma unroll
        for (int j = 0; j < 4; j++)
#pragma unroll
            for (int q = 0; q < 4; q++) acc[i][j][q] = 0.0f;

    uint32_t aregs[8];

    auto pick = [&](int it, const fp16*& A, const fp16*& W, int& K, int& k0) {
        if (it < n1) { A = (const fp16*)A1v; W = W1; K = K1; k0 = it << 5; }
        else         { A = A2p; W = W2; K = K2; k0 = (it - n1) << 5; }
    };

    auto issue = [&](int it, int stage) {
        const fp16 *A, *W; int K, k0;
        pick(it, A, W, K, k0);
        if (!A32) {
#pragma unroll
            for (int i = 0; i < 2; i++) {
                int idx = tid + i * 256;
                int r = idx >> 2, part = idx & 3;
                int gr = rowBase + r;
                uint32_t d = sb + OFF_A + stage * STG_T + r * LDSB + part * 16;
                if (gr < NN) cpa16(d, A + (size_t)gr * K + k0 + part * 8);
                else asm volatile("st.shared.v4.b32 [%0], {%1,%1,%1,%1};" :: "r"(d), "r"(0));
            }
        }
#pragma unroll
        for (int i = 0; i < 2; i++) {
            int idx = tid + i * 256;
            int n = idx >> 2, part = idx & 3;
            int gn = colBase + n;
            uint32_t d = sb + OFF_B + stage * STG_T + n * LDSB + part * 16;
            cpa16(d, W + (size_t)gn * K + k0 + part * 8);
        }
        asm volatile("cp.async.commit_group;");
    };

    auto loadAreg = [&](int it) {
        if (A32) {
            const float* Af = (const float*)A1v;
            int k0 = it << 5;
            int gr = rowBase + (tid >> 1);
            const float* p = Af + (size_t)gr * K1 + k0 + (tid & 1) * 16;
#pragma unroll
            for (int j = 0; j < 4; j++) {
                float4 v = (gr < NN) ? *(const float4*)(p + 4 * j)
                                     : make_float4(0.f, 0.f, 0.f, 0.f);
                aregs[2 * j] = pkh(v.x, v.y);
                aregs[2 * j + 1] = pkh(v.z, v.w);
            }
        }
    };

    auto storeAreg = [&](int stage) {
        if (A32) {
            uint32_t d = sb + OFF_A + stage * STG_T + (tid >> 1) * LDSB + (tid & 1) * 32;
            asm volatile("st.shared.v4.b32 [%0], {%1,%2,%3,%4};"
                         :: "r"(d), "r"(aregs[0]), "r"(aregs[1]),
                            "r"(aregs[2]), "r"(aregs[3]));
            asm volatile("st.shared.v4.b32 [%0], {%1,%2,%3,%4};"
                         :: "r"(d + 16), "r"(aregs[4]), "r"(aregs[5]),
                            "r"(aregs[6]), "r"(aregs[7]));
        }
    };

    auto compute = [&](int stage) {
#pragma unroll
        for (int ks = 0; ks < 2; ks++) {
            const int kk = ks * 16;
            uint32_t af[4][4];
#pragma unroll
            for (int mi = 0; mi < 4; mi++) {
                int row = warp_m * 64 + mi * 16 + (lane & 15);
                int kc = kk + ((lane >> 4) << 3);
                uint32_t ad = sb + OFF_A + stage * STG_T + row * LDSB + kc * 2;
                asm volatile("ldmatrix.sync.aligned.m8n8.x4.shared.b16 "
                             "{%0,%1,%2,%3}, [%4];"
                             : "=r"(af[mi][0]), "=r"(af[mi][1]),
                               "=r"(af[mi][2]), "=r"(af[mi][3]) : "r"(ad));
            }
            uint32_t bh[4][2];
#pragma unroll
            for (int pair = 0; pair < 2; pair++) {
                int rn = warp_n * 32 + pair * 16 + ((lane >> 4) << 3) + (lane & 7);
                int kc = kk + ((lane >> 3) & 1) * 8;
                uint32_t off = sb + OFF_B + stage * STG_T + rn * LDSB + kc * 2;
                asm volatile("ldmatrix.sync.aligned.m8n8.x4.shared.b16 "
                             "{%0,%1,%2,%3}, [%4];"
                             : "=r"(bh[2 * pair][0]), "=r"(bh[2 * pair][1]),
                               "=r"(bh[2 * pair + 1][0]), "=r"(bh[2 * pair + 1][1])
                             : "r"(off));
            }
#pragma unroll
            for (int mi = 0; mi < 4; mi++)
#pragma unroll
                for (int ni = 0; ni < 4; ni++)
                    mma_fp16(acc[mi][ni], af[mi], bh[ni]);
        }
    };

    // ---- prologue: prime 2 stages ----
    issue(0, 0);
    loadAreg(0);
    storeAreg(0);
    if (total > 1) {
        issue(1, 1);
        loadAreg(1);
        storeAreg(1);
    }

    // ---- 3-stage pipelined mainloop ----
    for (int it = 0; it < total; ++it) {
        const int stage = it % 3;
        if (it + 1 < total) asm volatile("cp.async.wait_group 1;");
        else               asm volatile("cp.async.wait_group 0;");
        __syncthreads();
        if (it + 2 < total) {
            issue(it + 2, (it + 2) % 3);
            loadAreg(it + 2);
            storeAreg((it + 2) % 3);
        }
        compute(stage);
    }

    const int g = lane >> 2, tg = lane & 3;

    if constexpr (!LN) {
        // ---- normal epilogue: fp16 out ----
#pragma unroll
        for (int mi = 0; mi < 4; mi++) {
#pragma unroll
            for (int ni = 0; ni < 4; ni++) {
                int col = colBase + warp_n * 32 + ni * 8 + tg * 2;
                float b0 = 0.f, b1 = 0.f;
                if (bias) { b0 = bias[col]; b1 = bias[col + 1]; }
                int row = rowBase + warp_m * 64 + mi * 16 + g;
                if (row < NN) {
                    float vx = acc[mi][ni][0] + b0, vy = acc[mi][ni][1] + b1;
                    if (reluflag) { vx = fmaxf(vx, 0.f); vy = fmaxf(vy, 0.f); }
                    fp162 h = __float22half2_rn(make_float2(vx, vy));
                    *(fp162*)(C + (size_t)row * M + col) = h;
                }
                if (row + 8 < NN) {
                    float vx = acc[mi][ni][2] + b0, vy = acc[mi][ni][3] + b1;
                    if (reluflag) { vx = fmaxf(vx, 0.f); vy = fmaxf(vy, 0.f); }
                    fp162 h = __float22half2_rn(make_float2(vx, vy));
                    *(fp162*)(C + (size_t)(row + 8) * M + col) = h;
                }
            }
        }
    } else {
        // ---- fused LayerNorm + dot(wm2) epilogue (M=128, gridDim.x=1) ----
        __syncthreads();
        float* sred = (float*)smem;             // [128][8]
        float* sdot = (float*)(smem + 4096);    // [128][4]
        float* sblk = (float*)(smem + 6144);    // [4]

        float b0[4], b1[4], w0[4], w1[4], l0[4], l1[4], m0[4], m1[4];
#pragma unroll
        for (int ni = 0; ni < 4; ni++) {
            int c = warp_n * 32 + ni * 8 + tg * 2;
            b0[ni] = bias[c];  b1[ni] = bias[c + 1];
            w0[ni] = lnw[c];   w1[ni] = lnw[c + 1];
            l0[ni] = lnb[c];   l1[ni] = lnb[c + 1];
            m0[ni] = wm2[c];   m1[ni] = wm2[c + 1];
        }

#pragma unroll
        for (int mi = 0; mi < 4; mi++) {
#pragma unroll
            for (int half = 0; half < 2; half++) {
                float ps = 0.f, pq = 0.f;
#pragma unroll
                for (int ni = 0; ni < 4; ni++) {
                    float v = acc[mi][ni][half * 2] + b0[ni];
                    float u = acc[mi][ni][half * 2 + 1] + b1[ni];
                    ps += v + u;
                    pq += v * v + u * u;
                }
                ps += __shfl_xor_sync(0xffffffffu, ps, 1);
                ps += __shfl_xor_sync(0xffffffffu, ps, 2);
                pq += __shfl_xor_sync(0xffffffffu, pq, 1);
                pq += __shfl_xor_sync(0xffffffffu, pq, 2);
                int r = warp_m * 64 + mi * 16 + g + half * 8;
                if (tg == 0) {
                    sred[r * 8 + warp_n * 2] = ps;
                    sred[r * 8 + warp_n * 2 + 1] = pq;
                }
            }
        }
        __syncthreads();

#pragma unroll
        for (int mi = 0; mi < 4; mi++) {
#pragma unroll
            for (int half = 0; half < 2; half++) {
                int r = warp_m * 64 + mi * 16 + g + half * 8;
                float sum = sred[r * 8 + 0] + sred[r * 8 + 2] + sred[r * 8 + 4] + sred[r * 8 + 6];
                float sq  = sred[r * 8 + 1] + sred[r * 8 + 3] + sred[r * 8 + 5] + sred[r * 8 + 7];
                float mu = sum * (1.0f / 128.0f);
                float var = sq * (1.0f / 128.0f) - mu * mu;
                float rs = rsqrtf(var + 1e-5f);
                float p = 0.f;
#pragma unroll
                for (int ni = 0; ni < 4; ni++) {
                    float v = acc[mi][ni][half * 2] + b0[ni];
                    float u = acc[mi][ni][half * 2 + 1] + b1[ni];
                    p += ((v - mu) * rs * w0[ni] + l0[ni]) * m0[ni]
                       + ((u - mu) * rs * w1[ni] + l1[ni]) * m1[ni];
                }
                p += __shfl_xor_sync(0xffffffffu, p, 1);
                p += __shfl_xor_sync(0xffffffffu, p, 2);
                if (tg == 0) sdot[r * 4 + warp_n] = p;
            }
        }
        __syncthreads();

        if (tid < 128) {
            int r = tid;
            int grow = rowBase + r;
            float y = 0.f;
            if (grow < NN)
                y = sdot[r * 4] + sdot[r * 4 + 1] + sdot[r * 4 + 2] + sdot[r * 4 + 3] + bm2[0];
#pragma unroll
            for (int o = 16; o; o >>= 1) y += __shfl_xor_sync(0xffffffffu, y, o);
            if ((tid & 31) == 0) sblk[tid >> 5] = y;
        }
        __syncthreads();
        if (tid == 0)
            g_part[poff + blockIdx.y] = sblk[0] + sblk[1] + sblk[2] + sblk[3];
    }
}

// ---------------- small utility kernels ----------------
__global__ void k_zero_int(int* p, int n) {
    int i = blockIdx.x * blockDim.x + threadIdx.x;
    if (i < n) p[i] = 0;
}

__global__ void k_copy_int(int* dst, const int* src, int n) {
    int i = blockIdx.x * blockDim.x + threadIdx.x;
    if (i < n) dst[i] = src[i];
}

__global__ void k_deg(const int* __restrict__ dst, int* __restrict__ deg) {
    int e = blockIdx.x * blockDim.x + threadIdx.x;
    if (e < EE) atomicAdd(&deg[dst[e]], 1);
}

__global__ void k_scan(const int* __restrict__ deg, int* __restrict__ rp, int n) {
    __shared__ int s[1024];
    int t = threadIdx.x;
    int chunk = (n + 1023) >> 10;
    int b = t * chunk;
    int e = b + chunk; if (e > n) e = n;
    int local = 0;
    for (int i = b; i < e && i < n; i++) local += deg[i];
    s[t] = local;
    __syncthreads();
    for (int off = 1; off < 1024; off <<= 1) {
        int v = (t >= off) ? s[t - off] : 0;
        __syncthreads();
        s[t] += v;
        __syncthreads();
    }
    int run = (t == 0) ? 0 : s[t - 1];
    for (int i = b; i < e && i < n; i++) { rp[i] = run; run += deg[i]; }
    if (t == 1023) rp[n] = s[1023];
}

__global__ void k_disinv(const int* __restrict__ deg, float* __restrict__ dis,
                         float* __restrict__ inv) {
    int i = blockIdx.x * blockDim.x + threadIdx.x;
    if (i < NN) {
        float d = (float)deg[i];
        dis[i] = rsqrtf(d + 1.0f);
        inv[i] = 1.0f / fmaxf(d, 1.0f);
    }
}

__global__ void k_place(const int* __restrict__ src, const int* __restrict__ dst,
                        int* __restrict__ cur, int* __restrict__ col) {
    int e = blockIdx.x * blockDim.x + threadIdx.x;
    if (e < EE) {
        int d = dst[e];
        int p = atomicAdd(&cur[d], 1);
        col[p] = src[e];
    }
}

// ---------------- helpers for fp16 gather ----------------
__device__ __forceinline__ void unp8(uint4 v, float* f) {
    float2 a = __half22float2(*(fp162*)&v.x);
    float2 b = __half22float2(*(fp162*)&v.y);
    float2 c = __half22float2(*(fp162*)&v.z);
    float2 d = __half22float2(*(fp162*)&v.w);
    f[0] = a.x; f[1] = a.y; f[2] = b.x; f[3] = b.y;
    f[4] = c.x; f[5] = c.y; f[6] = d.x; f[7] = d.y;
}

__device__ __forceinline__ uint4 pk8(const float* f) {
    fp162 a = __float22half2_rn(make_float2(f[0], f[1]));
    fp162 b = __float22half2_rn(make_float2(f[2], f[3]));
    fp162 c = __float22half2_rn(make_float2(f[4], f[5]));
    fp162 d = __float22half2_rn(make_float2(f[6], f[7]));
    return make_uint4(*(uint32_t*)&a, *(uint32_t*)&b, *(uint32_t*)&c, *(uint32_t*)&d);
}

// ---------------- GCN aggregation (warp per node, 2-edge unrolled) ----------------
// mode 0 (graph2, FIRST): X0 = relu(v); G1 = relu(v)+v
// mode 1 (graph1, SECOND): X0 += relu(v)
__global__ void k_gcn(const fp16* __restrict__ xw, const int* __restrict__ rp,
                      const int* __restrict__ col, const float* __restrict__ dis,
                      const float* __restrict__ bias, int mode) {
    int node = blockIdx.x * 8 + (threadIdx.x >> 5);
    int lane = threadIdx.x & 31;
    if (node >= NN) return;

    const uint4* xw4 = (const uint4*)xw;
    float acc[8] = {0, 0, 0, 0, 0, 0, 0, 0};
    int e0 = rp[node], e1 = rp[node + 1];
    int e = e0;
    for (; e + 1 < e1; e += 2) {
        int s0 = col[e], s1 = col[e + 1];
        float d0 = dis[s0], d1 = dis[s1];
        uint4 q0 = xw4[(size_t)s0 * 32 + lane];
        uint4 q1 = xw4[(size_t)s1 * 32 + lane];
        float f0[8], f1[8];
        unp8(q0, f0);
        unp8(q1, f1);
#pragma unroll
        for (int u = 0; u < 8; u++) acc[u] += f0[u] * d0 + f1[u] * d1;
    }
    if (e < e1) {
        int s = col[e];
        float ds = dis[s];
        float f[8];
        unp8(xw4[(size_t)s * 32 + lane], f);
#pragma unroll
        for (int u = 0; u < 8; u++) acc[u] += f[u] * ds;
    }
    float di = dis[node];
    float dii = di * di;
    float sf[8];
    unp8(xw4[(size_t)node * 32 + lane], sf);
    const float4* b4 = (const float4*)bias;
    float4 bb0 = b4[2 * lane], bb1 = b4[2 * lane + 1];
    float bb[8] = {bb0.x, bb0.y, bb0.z, bb0.w, bb1.x, bb1.y, bb1.z, bb1.w};

    float v[8], r[8];
#pragma unroll
    for (int u = 0; u < 8; u++) {
        v[u] = acc[u] * di + sf[u] * dii + bb[u];
        r[u] = fmaxf(v[u], 0.f);
    }

    size_t o = (size_t)node * 32 + lane;
    uint4* X04 = (uint4*)g_X0;
    if (mode == 0) {
        X04[o] = pk8(r);
        float gg[8];
#pragma unroll
        for (int u = 0; u < 8; u++) gg[u] = r[u] + v[u];
        ((uint4*)g_G1)[o] = pk8(gg);
    } else {
        float xs[8];
        unp8(X04[o], xs);
#pragma unroll
        for (int u = 0; u < 8; u++) xs[u] += r[u];
        X04[o] = pk8(xs);
    }
}

// ---------------- SAGE mean aggregation (warp per node, 2-edge unrolled) ----------
__global__ void k_sage(const fp16* __restrict__ feat, const int* __restrict__ rp,
                       const int* __restrict__ col, const float* __restrict__ inv,
                       fp16* __restrict__ out) {
    int node = blockIdx.x * 8 + (threadIdx.x >> 5);
    int lane = threadIdx.x & 31;
    if (node >= NN) return;

    const uint4* f4 = (const uint4*)feat;
    float acc[8] = {0, 0, 0, 0, 0, 0, 0, 0};
    int e0 = rp[node], e1 = rp[node + 1];
    int e = e0;
    for (; e + 1 < e1; e += 2) {
        int s0 = col[e], s1 = col[e + 1];
        uint4 q0 = f4[(size_t)s0 * 32 + lane];
        uint4 q1 = f4[(size_t)s1 * 32 + lane];
        float f0[8], f1[8];
        unp8(q0, f0);
        unp8(q1, f1);
#pragma unroll
        for (int u = 0; u < 8; u++) acc[u] += f0[u] + f1[u];
    }
    if (e < e1) {
        int s = col[e];
        float f[8];
        unp8(f4[(size_t)s * 32 + lane], f);
#pragma unroll
        for (int u = 0; u < 8; u++) acc[u] += f[u];
    }
    float ic = inv[node];
#pragma unroll
    for (int u = 0; u < 8; u++) acc[u] *= ic;
    ((uint4*)out)[(size_t)node * 32 + lane] = pk8(acc);
}

// ---------------- final reduction ----------------
__global__ void k_final(float* out) {
    __shared__ float s[1024];
    int t = threadIdx.x;
    float v = 0;
    for (int i = t; i < 1564; i += 1024) v += g_part[i];
    s[t] = v;
    __syncthreads();
    for (int off = 512; off; off >>= 1) {
        if (t < off) s[t] += s[t + off];
        __syncthreads();
    }
    if (t == 0) out[0] = s[0] * (1.0f / (2.0f * (float)NN));
}

// ---------------- host ----------------
static void* symaddr(const void* s) {
    void* p = nullptr;
    cudaGetSymbolAddress(&p, s);
    return p;
}

static cudaStream_t mkstream() {
    cudaStream_t s;
    cudaStreamCreateWithFlags(&s, cudaStreamNonBlocking);
    return s;
}
static cudaEvent_t mkevent() {
    cudaEvent_t e;
    cudaEventCreateWithFlags(&e, cudaEventDisableTiming);
    return e;
}

extern "C" void kernel_launch(void* const* d_in, const int* in_sizes, int n_in,
                              void* d_out, int out_size) {
    static cudaStream_t s1 = mkstream();
    static cudaStream_t s2 = mkstream();
    static cudaEvent_t eF  = mkevent();
    static cudaEvent_t eW2 = mkevent();   // GEMM2 done
    static cudaEvent_t e2  = mkevent();   // CSR + weights done
    static cudaEvent_t eR2 = mkevent();   // gcn_b done (X0=r2, G1 ready)
    static cudaEvent_t eB  = mkevent();   // branch B done

    const float* x   = (const float*)d_in[0];
    const float* x1  = (const float*)d_in[1];
    const int*   ei  = (const int*)d_in[2];
    const int*   ei1 = (const int*)d_in[3];
    const float* Wg1 = (const float*)d_in[4];
    const float* bg1 = (const float*)d_in[5];
    const float* Wg2 = (const float*)d_in[6];
    const float* bg2 = (const float*)d_in[7];
    const float* Wl1 = (const float*)d_in[8];
    const float* bl1 = (const float*)d_in[9];
    const float* Wr1 = (const float*)d_in[10];
    const float* Wl2 = (const float*)d_in[11];
    const float* bl2 = (const float*)d_in[12];
    const float* Wr2 = (const float*)d_in[13];
    const float* Wm1 = (const float*)d_in[14];
    const float* bm1 = (const float*)d_in[15];
    const float* lnw = (const float*)d_in[16];
    const float* lnb = (const float*)d_in[17];
    const float* Wm2 = (const float*)d_in[18];
    const float* bm2 = (const float*)d_in[19];

    const int* src1 = ei;
    const int* dst1 = ei + EE;
    const int* src2 = ei1;
    const int* dst2 = ei1 + EE;

    fp16* XW1  = (fp16*)symaddr(g_XW1);
    fp16* XW2  = (fp16*)symaddr(g_XW2);
    fp16* X0   = (fp16*)symaddr(g_X0);
    fp16* G1   = (fp16*)symaddr(g_G1);
    fp16* MEAN = (fp16*)symaddr(g_MEAN);
    fp16* A1   = (fp16*)symaddr(g_A1);
    fp16* A1B  = (fp16*)symaddr(g_A1B);
    float* dis1 = (float*)symaddr(g_dis1);
    float* dis2 = (float*)symaddr(g_dis2);
    float* inv1 = (float*)symaddr(g_inv1);
    float* inv2 = (float*)symaddr(g_inv2);
    int* deg1 = (int*)symaddr(g_deg1);
    int* deg2 = (int*)symaddr(g_deg2);
    int* rp1  = (int*)symaddr(g_rp1);
    int* rp2  = (int*)symaddr(g_rp2);
    int* cur1 = (int*)symaddr(g_cur1);
    int* cur2 = (int*)symaddr(g_cur2);
    int* col1 = (int*)symaddr(g_col1);
    int* col2 = (int*)symaddr(g_col2);
    fp16* wt = (fp16*)symaddr(g_wt);

    fp16* MEANB = XW2;   // XW2 dead after gcn_b

    const int TB = 256;
    const int gN = (NN + TB - 1) / TB;
    const int gE = (EE + TB - 1) / TB;

    cudaFuncSetAttribute(k_mma<true, false>,  cudaFuncAttributeMaxDynamicSharedMemorySize, SMEM_MMA);
    cudaFuncSetAttribute(k_mma<false, false>, cudaFuncAttributeMaxDynamicSharedMemorySize, SMEM_MMA);
    cudaFuncSetAttribute(k_mma<false, true>,  cudaFuncAttributeMaxDynamicSharedMemorySize, SMEM_MMA);

    const int GY = (NN + 127) / 128;  // 782
    dim3 g256(HH / 128, GY);          // (2, 782)
    dim3 g128(HG / 128, GY);          // (1, 782)
    const int gW = NN / 8;

    // ---- fork ----
    cudaEventRecord(eF, 0);
    cudaStreamWaitEvent(s1, eF, 0);
    cudaStreamWaitEvent(s2, eF, 0);

    // ---- s1: graph-2 chain (fully independent branch B) ----
    k_wt<<<(FF * HH + 255) / 256, 256, 0, s1>>>(Wg2, wt + OWG2, FF, HH);
    k_mma<true, false><<<g256, 256, SMEM_MMA, s1>>>(
        x1, wt + OWG2, FF, nullptr, nullptr, 0, XW2, HH, nullptr, 0,
        nullptr, nullptr, nullptr, nullptr, 0);
    cudaEventRecord(eW2, s1);

    // ---- s2: CSR build + SAGE/MLP weight transposes ----
    k_wt<<<(HH * HG + 255) / 256, 256, 0, s2>>>(Wl1, wt + OWL1, HH, HG);
    k_wt<<<(HH * HG + 255) / 256, 256, 0, s2>>>(Wr1, wt + OWR1, HH, HG);
    k_wt<<<(HH * HG + 255) / 256, 256, 0, s2>>>(Wl2, wt + OWL2, HH, HG);
    k_wt<<<(HH * HG + 255) / 256, 256, 0, s2>>>(Wr2, wt + OWR2, HH, HG);
    k_wt<<<(HG * HG + 255) / 256, 256, 0, s2>>>(Wm1, wt + OWM1, HG, HG);
    k_zero_int<<<gN, TB, 0, s2>>>(deg1, NN);
    k_zero_int<<<gN, TB, 0, s2>>>(deg2, NN);
    k_deg<<<gE, TB, 0, s2>>>(dst1, deg1);
    k_deg<<<gE, TB, 0, s2>>>(dst2, deg2);
    k_scan<<<1, 1024, 0, s2>>>(deg1, rp1, NN);
    k_scan<<<1, 1024, 0, s2>>>(deg2, rp2, NN);
    k_disinv<<<gN, TB, 0, s2>>>(deg1, dis1, inv1);
    k_disinv<<<gN, TB, 0, s2>>>(deg2, dis2, inv2);
    k_copy_int<<<gN, TB, 0, s2>>>(cur1, rp1, NN);
    k_copy_int<<<gN, TB, 0, s2>>>(cur2, rp2, NN);
    k_place<<<gE, TB, 0, s2>>>(src1, dst1, cur1, col1);
    k_place<<<gE, TB, 0, s2>>>(src2, dst2, cur2, col2);
    cudaEventRecord(e2, s2);

    // ---- s1 continues branch B (needs CSR) ----
    cudaStreamWaitEvent(s1, e2, 0);
    k_gcn<<<gW, 256, 0, s1>>>(XW2, rp2, col2, dis2, bg2, 0);   // X0=r2, G1=r2+v2
    cudaEventRecord(eR2, s1);
    k_sage<<<gW, 256, 0, s1>>>(G1, rp2, col2, inv2, MEANB);
    k_mma<false, false><<<g128, 256, SMEM_MMA, s1>>>(
        MEANB, wt + OWL2, HH, G1, wt + OWR2, HH, A1B, HG, bl2, 1,
        nullptr, nullptr, nullptr, nullptr, 0);
    k_mma<false, true><<<g128, 256, SMEM_MMA, s1>>>(
        A1B, wt + OWM1, HG, nullptr, nullptr, 0, nullptr, HG, bm1, 0,
        lnw, lnb, Wm2, bm2, 782);
    cudaEventRecord(eB, s1);

    // ---- s0: graph-1 GCN GEMM (serialized after GEMM2 to prioritize branch B) ----
    k_wt<<<(FF * HH + 255) / 256, 256, 0, 0>>>(Wg1, wt + OWG1, FF, HH);
    cudaStreamWaitEvent(0, eW2, 0);
    k_mma<true, false><<<g256, 256, SMEM_MMA, 0>>>(
        x, wt + OWG1, FF, nullptr, nullptr, 0, XW1, HH, nullptr, 0,
        nullptr, nullptr, nullptr, nullptr, 0);

    // ---- s0: branch A ----
    cudaStreamWaitEvent(0, eR2, 0);
    k_gcn<<<gW, 256, 0, 0>>>(XW1, rp1, col1, dis1, bg1, 1);    // X0 += r1
    k_sage<<<gW, 256, 0, 0>>>(X0, rp1, col1, inv1, MEAN);
    k_mma<false, false><<<g128, 256, SMEM_MMA, 0>>>(
        MEAN, wt + OWL1, HH, X0, wt + OWR1, HH, A1, HG, bl1, 1,
        nullptr, nullptr, nullptr, nullptr, 0);
    k_mma<false, true><<<g128, 256, SMEM_MMA, 0>>>(
        A1, wt + OWM1, HG, nullptr, nullptr, 0, nullptr, HG, bm1, 0,
        lnw, lnb, Wm2, bm2, 0);

    // ---- join + final reduction ----
    cudaStreamWaitEvent(0, eB, 0);
    k_final<<<1, 1024, 0, 0>>>((float*)d_out);
}